// round 4
// baseline (speedup 1.0000x reference)
#include <cuda_runtime.h>

// ---------------------------------------------------------------------------
// MultiStageResidualVQ (eval math):
//   per row r: res=z[r]; for s in 0..2: idx=argmax(res.cb_s^T - 0.5|cb|^2);
//   loss += 1.25*mean((res-cb[idx])^2); res -= cb[idx];
//   q_total = z - res_final; composed = idx0 + 1024*idx1 + 1024^2*idx2;
//   perp_s  = exp(-sum p log(p+1e-10)),  p = counts/N
// Fused single main kernel: residual lives transposed in SMEM, SGEMM-style
// 128x128 fp32 tiles vs the 1024-codeword codebook per stage.
// R2 fix: SMEM row strides multiples of 4 floats so LDS.128 is 16B-aligned.
// R3/R4: resubmit unchanged — broker timeouts, kernel has never run.
// ---------------------------------------------------------------------------

#define DEPTH 3
#define KCB   1024
#define DIM   256
#define TM    128
#define AS    132          // resT row stride (multiple of 4 for float4 align)
#define BS    132          // Ct row stride   (multiple of 4 for float4 align)
#define NTHREADS 256

__device__ float d_hE2[DEPTH * KCB];     // 0.5 * |cb_k|^2 per stage
__device__ int   d_counts[DEPTH * KCB];  // code usage histogram
__device__ float d_blockSSE[512];        // per-block SSE partials (deterministic)

// ---------------------------------------------------------------------------
__global__ void vq_init_kernel(const float* __restrict__ cb) {
    int gid = blockIdx.x * blockDim.x + threadIdx.x;
    if (gid < DEPTH * KCB) d_counts[gid] = 0;

    int warp = threadIdx.x >> 5, lane = threadIdx.x & 31;
    int cw = blockIdx.x * 8 + warp;                 // one codeword per warp
    if (cw < DEPTH * KCB) {
        const float* row = cb + (size_t)cw * DIM;
        float s = 0.f;
        #pragma unroll
        for (int i = lane; i < DIM; i += 32) { float v = row[i]; s += v * v; }
        #pragma unroll
        for (int off = 16; off; off >>= 1) s += __shfl_xor_sync(0xffffffffu, s, off);
        if (lane == 0) d_hE2[cw] = 0.5f * s;
    }
}

// ---------------------------------------------------------------------------
extern __shared__ float sm[];

__global__ __launch_bounds__(NTHREADS, 1)
void vq_main_kernel(const float* __restrict__ z,
                    const float* __restrict__ cb,
                    float* __restrict__ out_q,
                    float* __restrict__ out_comp) {
    float* resT = sm;                 // [DIM][AS]  transposed residual
    float* Ct   = sm + DIM * AS;      // [64][BS]   transposed codebook tile

    __shared__ int   s_idx[TM];
    __shared__ int   s_comp[TM];
    __shared__ float s_red[8];

    const int tid = threadIdx.x;
    const int tx = tid & 15, ty = tid >> 4;
    const int row0 = blockIdx.x * TM;

    // ---- load z rows into transposed SMEM residual ----
    #pragma unroll
    for (int u = 0; u < 32; ++u) {
        int lin = tid + u * NTHREADS;          // 0..8191 float4s
        int row = lin >> 6;                    // 64 float4 per row
        int dd4 = lin & 63;
        float4 v = *(const float4*)(z + (size_t)(row0 + row) * DIM + dd4 * 4);
        int d = dd4 * 4;
        resT[(d + 0) * AS + row] = v.x;
        resT[(d + 1) * AS + row] = v.y;
        resT[(d + 2) * AS + row] = v.z;
        resT[(d + 3) * AS + row] = v.w;
    }

    float sse = 0.f;
    const int rowE = tid & 127, half = tid >> 7;   // epilogue mapping

    for (int s = 0; s < DEPTH; ++s) {
        const float* cbs = cb + (size_t)s * KCB * DIM;
        const float* hs  = d_hE2 + s * KCB;

        float bestv[8]; int besti[8];
        #pragma unroll
        for (int r = 0; r < 8; ++r) { bestv[r] = -1e30f; besti[r] = 0; }

        for (int kb = 0; kb < KCB / 128; ++kb) {
            float acc[8][8];
            #pragma unroll
            for (int r = 0; r < 8; ++r)
                #pragma unroll
                for (int j = 0; j < 8; ++j) acc[r][j] = 0.f;

            for (int dk = 0; dk < DIM; dk += 64) {
                __syncthreads();
                // load 128 codes x 64 dims, transposed into Ct
                #pragma unroll
                for (int u = 0; u < 8; ++u) {
                    int lin = tid + u * NTHREADS;      // 0..2047
                    int code = lin >> 4, d4 = lin & 15;
                    float4 v = *(const float4*)(cbs + (size_t)(kb * 128 + code) * DIM
                                                + dk + d4 * 4);
                    int d = d4 * 4;
                    Ct[(d + 0) * BS + code] = v.x;
                    Ct[(d + 1) * BS + code] = v.y;
                    Ct[(d + 2) * BS + code] = v.z;
                    Ct[(d + 3) * BS + code] = v.w;
                }
                __syncthreads();

                #pragma unroll 8
                for (int d = 0; d < 64; ++d) {
                    const float* rA = resT + (dk + d) * AS;
                    const float* rB = Ct + d * BS;
                    float4 a0 = *(const float4*)(rA + ty * 4);
                    float4 a1 = *(const float4*)(rA + 64 + ty * 4);
                    float4 b0 = *(const float4*)(rB + tx * 4);
                    float4 b1 = *(const float4*)(rB + 64 + tx * 4);
                    float a[8] = {a0.x, a0.y, a0.z, a0.w, a1.x, a1.y, a1.z, a1.w};
                    float b[8] = {b0.x, b0.y, b0.z, b0.w, b1.x, b1.y, b1.z, b1.w};
                    #pragma unroll
                    for (int r = 0; r < 8; ++r)
                        #pragma unroll
                        for (int j = 0; j < 8; ++j)
                            acc[r][j] = fmaf(a[r], b[j], acc[r][j]);
                }
            }

            // fold this 128-code chunk into per-row running argmax
            #pragma unroll
            for (int j = 0; j < 8; ++j) {
                int cl = (j < 4) ? (tx * 4 + j) : (64 + tx * 4 + (j - 4));
                int cg = kb * 128 + cl;
                float h = hs[cg];
                #pragma unroll
                for (int r = 0; r < 8; ++r) {
                    float sc = acc[r][j] - h;
                    if (sc > bestv[r] || (sc == bestv[r] && cg < besti[r])) {
                        bestv[r] = sc; besti[r] = cg;
                    }
                }
            }
        }

        // reduce across the 16 tx-lanes sharing the same rows
        #pragma unroll
        for (int r = 0; r < 8; ++r) {
            float v = bestv[r]; int idx = besti[r];
            #pragma unroll
            for (int off = 8; off; off >>= 1) {
                float ov = __shfl_xor_sync(0xffffffffu, v, off);
                int   oi = __shfl_xor_sync(0xffffffffu, idx, off);
                if (ov > v || (ov == v && oi < idx)) { v = ov; idx = oi; }
            }
            if (tx == 0) {
                int rg = (r < 4) ? (ty * 4 + r) : (64 + ty * 4 + (r - 4));
                s_idx[rg] = idx;
                if (s == 0)      s_comp[rg] = idx;
                else if (s == 1) s_comp[rg] += idx * 1024;
                else             s_comp[rg] += idx * 1048576;
            }
        }
        __syncthreads();

        // residual update + SSE + histogram
        int myidx = s_idx[rowE];
        if (half == 0) atomicAdd(&d_counts[s * KCB + myidx], 1);
        const float* crow = cbs + (size_t)myidx * DIM;
        #pragma unroll 8
        for (int i = 0; i < 128; i += 4) {
            int d = half * 128 + i;
            float4 c = *(const float4*)(crow + d);
            float r0 = resT[(d + 0) * AS + rowE] - c.x;
            float r1 = resT[(d + 1) * AS + rowE] - c.y;
            float r2 = resT[(d + 2) * AS + rowE] - c.z;
            float r3 = resT[(d + 3) * AS + rowE] - c.w;
            resT[(d + 0) * AS + rowE] = r0;
            resT[(d + 1) * AS + rowE] = r1;
            resT[(d + 2) * AS + rowE] = r2;
            resT[(d + 3) * AS + rowE] = r3;
            sse += r0 * r0 + r1 * r1 + r2 * r2 + r3 * r3;
        }
        // visibility of resT updates for the next stage is covered by the
        // __syncthreads() at the top of the next (kb,dk) tile load.
    }

    // ---- q_total = z - res_final ----
    #pragma unroll 8
    for (int i = 0; i < 128; i += 4) {
        int d = half * 128 + i;
        float4 zv = *(const float4*)(z + (size_t)(row0 + rowE) * DIM + d);
        float4 o;
        o.x = zv.x - resT[(d + 0) * AS + rowE];
        o.y = zv.y - resT[(d + 1) * AS + rowE];
        o.z = zv.z - resT[(d + 2) * AS + rowE];
        o.w = zv.w - resT[(d + 3) * AS + rowE];
        *(float4*)(out_q + (size_t)(row0 + rowE) * DIM + d) = o;
    }

    // ---- composed indices ----
    if (out_comp != nullptr && tid < TM)
        out_comp[row0 + tid] = (float)s_comp[tid];

    // ---- deterministic per-block SSE partial ----
    #pragma unroll
    for (int off = 16; off; off >>= 1) sse += __shfl_xor_sync(0xffffffffu, sse, off);
    int warp = tid >> 5, lane = tid & 31;
    if (lane == 0) s_red[warp] = sse;
    __syncthreads();
    if (tid == 0) {
        float t = 0.f;
        #pragma unroll
        for (int w = 0; w < 8; ++w) t += s_red[w];
        d_blockSSE[blockIdx.x] = t;
    }
}

// ---------------------------------------------------------------------------
__global__ void vq_finalize_kernel(float* out_loss, float* out_perp,
                                   int nblocks, float inv_total, float inv_n) {
    __shared__ float red[1024];
    int tid = threadIdx.x;

    // vq_loss: fixed-order tree over per-block partials -> deterministic
    float v = (tid < nblocks) ? d_blockSSE[tid] : 0.f;
    red[tid] = v;
    __syncthreads();
    for (int s2 = 512; s2; s2 >>= 1) {
        if (tid < s2) red[tid] += red[tid + s2];
        __syncthreads();
    }
    if (tid == 0 && out_loss != nullptr)
        *out_loss = 1.25f * red[0] * inv_total;
    __syncthreads();

    // perplexities
    for (int s = 0; s < DEPTH; ++s) {
        float p = (float)d_counts[s * KCB + tid] * inv_n;
        red[tid] = p * logf(p + 1e-10f);
        __syncthreads();
        for (int s2 = 512; s2; s2 >>= 1) {
            if (tid < s2) red[tid] += red[tid + s2];
            __syncthreads();
        }
        if (tid == 0 && out_perp != nullptr) out_perp[s] = expf(-red[0]);
        __syncthreads();
    }
}

// ---------------------------------------------------------------------------
extern "C" void kernel_launch(void* const* d_in, const int* in_sizes, int n_in,
                              void* d_out, int out_size) {
    const float* z  = (const float*)d_in[0];
    const float* cb = (const float*)d_in[1];
    float* out = (float*)d_out;

    const int N = in_sizes[0] / DIM;          // 32768 rows
    const long qtot = (long)N * DIM;          // 8388608

    float* out_loss = nullptr;
    float* out_comp = nullptr;
    float* out_perp = nullptr;
    if ((long)out_size >= qtot + 1 + N + DEPTH) {
        out_loss = out + qtot;
        out_comp = out + qtot + 1;
        out_perp = out + qtot + 1 + N;
    }

    size_t smem = (size_t)(DIM * AS + 64 * BS) * sizeof(float);  // ~165 KB
    cudaFuncSetAttribute(vq_main_kernel,
                         cudaFuncAttributeMaxDynamicSharedMemorySize, (int)smem);

    vq_init_kernel<<<(DEPTH * KCB + 7) / 8, 256>>>(cb);
    vq_main_kernel<<<N / TM, NTHREADS, smem>>>(z, cb, out, out_comp);
    vq_finalize_kernel<<<1, 1024>>>(out_loss, out_perp, N / TM,
                                    1.0f / (float)qtot, 1.0f / (float)N);
}

// round 7
// speedup vs baseline: 1.0575x; 1.0575x over previous
#include <cuda_runtime.h>

// ---------------------------------------------------------------------------
// MultiStageResidualVQ — R5/R6/R7: packed fma.rn.f32x2 inner product.
// R4 measured 1350us = 99% of scalar fp32 FFMA roofline (1339us @2.03GHz).
// FFMA2 (PTX fma.rn.f32x2, per-lane exact fp32) doubles fp32 MAC throughput.
// Accumulators packed along the code axis: acc2[r][p] = (code 2p, code 2p+1).
// B pairs are adjacent floats in Ct rows (free register-pair reinterpret);
// A is duplicated into both halves with one mov.b64 per (r,d).
// All numerics are bit-identical to the scalar version.
// R7: resubmit unchanged — R5/R6 never ran (broker timeouts).
// ---------------------------------------------------------------------------

#define DEPTH 3
#define KCB   1024
#define DIM   256
#define TM    128
#define AS    132          // resT row stride (multiple of 4 for float4 align)
#define BS    132          // Ct row stride   (multiple of 4 for float4 align)
#define NTHREADS 256

typedef unsigned long long u64;

__device__ __forceinline__ void ffma2(u64& acc, u64 a, u64 b) {
    asm("fma.rn.f32x2 %0, %1, %2, %0;" : "+l"(acc) : "l"(a), "l"(b));
}
__device__ __forceinline__ u64 dup_f32(float a) {
    u64 r;
    asm("mov.b64 %0, {%1, %1};" : "=l"(r) : "f"(a));
    return r;
}
__device__ __forceinline__ void unpack2(float& lo, float& hi, u64 v) {
    asm("mov.b64 {%0, %1}, %2;" : "=f"(lo), "=f"(hi) : "l"(v));
}

union F4U2 { float4 f4; u64 u2[2]; };

__device__ float d_hE2[DEPTH * KCB];     // 0.5 * |cb_k|^2 per stage
__device__ int   d_counts[DEPTH * KCB];  // code usage histogram
__device__ float d_blockSSE[512];        // per-block SSE partials (deterministic)

// ---------------------------------------------------------------------------
__global__ void vq_init_kernel(const float* __restrict__ cb) {
    int gid = blockIdx.x * blockDim.x + threadIdx.x;
    if (gid < DEPTH * KCB) d_counts[gid] = 0;

    int warp = threadIdx.x >> 5, lane = threadIdx.x & 31;
    int cw = blockIdx.x * 8 + warp;                 // one codeword per warp
    if (cw < DEPTH * KCB) {
        const float* row = cb + (size_t)cw * DIM;
        float s = 0.f;
        #pragma unroll
        for (int i = lane; i < DIM; i += 32) { float v = row[i]; s += v * v; }
        #pragma unroll
        for (int off = 16; off; off >>= 1) s += __shfl_xor_sync(0xffffffffu, s, off);
        if (lane == 0) d_hE2[cw] = 0.5f * s;
    }
}

// ---------------------------------------------------------------------------
extern __shared__ float sm[];

__global__ __launch_bounds__(NTHREADS, 1)
void vq_main_kernel(const float* __restrict__ z,
                    const float* __restrict__ cb,
                    float* __restrict__ out_q,
                    float* __restrict__ out_comp) {
    float* resT = sm;                 // [DIM][AS]  transposed residual
    float* Ct   = sm + DIM * AS;      // [64][BS]   transposed codebook tile

    __shared__ int   s_idx[TM];
    __shared__ int   s_comp[TM];
    __shared__ float s_red[8];

    const int tid = threadIdx.x;
    const int tx = tid & 15, ty = tid >> 4;
    const int row0 = blockIdx.x * TM;

    // ---- load z rows into transposed SMEM residual ----
    #pragma unroll
    for (int u = 0; u < 32; ++u) {
        int lin = tid + u * NTHREADS;          // 0..8191 float4s
        int row = lin >> 6;                    // 64 float4 per row
        int dd4 = lin & 63;
        float4 v = *(const float4*)(z + (size_t)(row0 + row) * DIM + dd4 * 4);
        int d = dd4 * 4;
        resT[(d + 0) * AS + row] = v.x;
        resT[(d + 1) * AS + row] = v.y;
        resT[(d + 2) * AS + row] = v.z;
        resT[(d + 3) * AS + row] = v.w;
    }

    float sse = 0.f;
    const int rowE = tid & 127, half = tid >> 7;   // epilogue mapping

    for (int s = 0; s < DEPTH; ++s) {
        const float* cbs = cb + (size_t)s * KCB * DIM;
        const float* hs  = d_hE2 + s * KCB;

        float bestv[8]; int besti[8];
        #pragma unroll
        for (int r = 0; r < 8; ++r) { bestv[r] = -1e30f; besti[r] = 0; }

        for (int kb = 0; kb < KCB / 128; ++kb) {
            // packed accumulators: acc2[r][p] holds codes (2p, 2p+1) of this
            // thread's 8-code column group (p 0..1 -> b0, p 2..3 -> b1)
            u64 acc2[8][4];
            #pragma unroll
            for (int r = 0; r < 8; ++r)
                #pragma unroll
                for (int p = 0; p < 4; ++p) acc2[r][p] = 0ull;

            for (int dk = 0; dk < DIM; dk += 64) {
                __syncthreads();
                // load 128 codes x 64 dims, transposed into Ct
                #pragma unroll
                for (int u = 0; u < 8; ++u) {
                    int lin = tid + u * NTHREADS;      // 0..2047
                    int code = lin >> 4, d4 = lin & 15;
                    float4 v = *(const float4*)(cbs + (size_t)(kb * 128 + code) * DIM
                                                + dk + d4 * 4);
                    int d = d4 * 4;
                    Ct[(d + 0) * BS + code] = v.x;
                    Ct[(d + 1) * BS + code] = v.y;
                    Ct[(d + 2) * BS + code] = v.z;
                    Ct[(d + 3) * BS + code] = v.w;
                }
                __syncthreads();

                #pragma unroll 8
                for (int d = 0; d < 64; ++d) {
                    const float* rA = resT + (dk + d) * AS;
                    const float* rB = Ct + d * BS;
                    float4 a0 = *(const float4*)(rA + ty * 4);
                    float4 a1 = *(const float4*)(rA + 64 + ty * 4);
                    F4U2 b0, b1;
                    b0.f4 = *(const float4*)(rB + tx * 4);
                    b1.f4 = *(const float4*)(rB + 64 + tx * 4);
                    float a[8] = {a0.x, a0.y, a0.z, a0.w, a1.x, a1.y, a1.z, a1.w};
                    #pragma unroll
                    for (int r = 0; r < 8; ++r) {
                        u64 ar = dup_f32(a[r]);
                        ffma2(acc2[r][0], ar, b0.u2[0]);
                        ffma2(acc2[r][1], ar, b0.u2[1]);
                        ffma2(acc2[r][2], ar, b1.u2[0]);
                        ffma2(acc2[r][3], ar, b1.u2[1]);
                    }
                }
            }

            // fold this 128-code chunk into per-row running argmax
            #pragma unroll
            for (int p = 0; p < 4; ++p) {
                int j0 = 2 * p;                        // codes j0, j0+1
                int cl0 = (j0 < 4) ? (tx * 4 + j0) : (64 + tx * 4 + (j0 - 4));
                int cg0 = kb * 128 + cl0;
                float h0 = hs[cg0], h1 = hs[cg0 + 1];
                #pragma unroll
                for (int r = 0; r < 8; ++r) {
                    float v0, v1;
                    unpack2(v0, v1, acc2[r][p]);
                    float sc0 = v0 - h0;
                    float sc1 = v1 - h1;
                    if (sc0 > bestv[r] || (sc0 == bestv[r] && cg0 < besti[r])) {
                        bestv[r] = sc0; besti[r] = cg0;
                    }
                    if (sc1 > bestv[r] || (sc1 == bestv[r] && cg0 + 1 < besti[r])) {
                        bestv[r] = sc1; besti[r] = cg0 + 1;
                    }
                }
            }
        }

        // reduce across the 16 tx-lanes sharing the same rows
        #pragma unroll
        for (int r = 0; r < 8; ++r) {
            float v = bestv[r]; int idx = besti[r];
            #pragma unroll
            for (int off = 8; off; off >>= 1) {
                float ov = __shfl_xor_sync(0xffffffffu, v, off);
                int   oi = __shfl_xor_sync(0xffffffffu, idx, off);
                if (ov > v || (ov == v && oi < idx)) { v = ov; idx = oi; }
            }
            if (tx == 0) {
                int rg = (r < 4) ? (ty * 4 + r) : (64 + ty * 4 + (r - 4));
                s_idx[rg] = idx;
                if (s == 0)      s_comp[rg] = idx;
                else if (s == 1) s_comp[rg] += idx * 1024;
                else             s_comp[rg] += idx * 1048576;
            }
        }
        __syncthreads();

        // residual update + SSE + histogram
        int myidx = s_idx[rowE];
        if (half == 0) atomicAdd(&d_counts[s * KCB + myidx], 1);
        const float* crow = cbs + (size_t)myidx * DIM;
        #pragma unroll 8
        for (int i = 0; i < 128; i += 4) {
            int d = half * 128 + i;
            float4 c = *(const float4*)(crow + d);
            float r0 = resT[(d + 0) * AS + rowE] - c.x;
            float r1 = resT[(d + 1) * AS + rowE] - c.y;
            float r2 = resT[(d + 2) * AS + rowE] - c.z;
            float r3 = resT[(d + 3) * AS + rowE] - c.w;
            resT[(d + 0) * AS + rowE] = r0;
            resT[(d + 1) * AS + rowE] = r1;
            resT[(d + 2) * AS + rowE] = r2;
            resT[(d + 3) * AS + rowE] = r3;
            sse += r0 * r0 + r1 * r1 + r2 * r2 + r3 * r3;
        }
        // visibility of resT updates for the next stage is covered by the
        // __syncthreads() at the top of the next (kb,dk) tile load.
    }

    // ---- q_total = z - res_final ----
    #pragma unroll 8
    for (int i = 0; i < 128; i += 4) {
        int d = half * 128 + i;
        float4 zv = *(const float4*)(z + (size_t)(row0 + rowE) * DIM + d);
        float4 o;
        o.x = zv.x - resT[(d + 0) * AS + rowE];
        o.y = zv.y - resT[(d + 1) * AS + rowE];
        o.z = zv.z - resT[(d + 2) * AS + rowE];
        o.w = zv.w - resT[(d + 3) * AS + rowE];
        *(float4*)(out_q + (size_t)(row0 + rowE) * DIM + d) = o;
    }

    // ---- composed indices ----
    if (out_comp != nullptr && tid < TM)
        out_comp[row0 + tid] = (float)s_comp[tid];

    // ---- deterministic per-block SSE partial ----
    #pragma unroll
    for (int off = 16; off; off >>= 1) sse += __shfl_xor_sync(0xffffffffu, sse, off);
    int warp = tid >> 5, lane = tid & 31;
    if (lane == 0) s_red[warp] = sse;
    __syncthreads();
    if (tid == 0) {
        float t = 0.f;
        #pragma unroll
        for (int w = 0; w < 8; ++w) t += s_red[w];
        d_blockSSE[blockIdx.x] = t;
    }
}

// ---------------------------------------------------------------------------
__global__ void vq_finalize_kernel(float* out_loss, float* out_perp,
                                   int nblocks, float inv_total, float inv_n) {
    __shared__ float red[1024];
    int tid = threadIdx.x;

    // vq_loss: fixed-order tree over per-block partials -> deterministic
    float v = (tid < nblocks) ? d_blockSSE[tid] : 0.f;
    red[tid] = v;
    __syncthreads();
    for (int s2 = 512; s2; s2 >>= 1) {
        if (tid < s2) red[tid] += red[tid + s2];
        __syncthreads();
    }
    if (tid == 0 && out_loss != nullptr)
        *out_loss = 1.25f * red[0] * inv_total;
    __syncthreads();

    // perplexities
    for (int s = 0; s < DEPTH; ++s) {
        float p = (float)d_counts[s * KCB + tid] * inv_n;
        red[tid] = p * logf(p + 1e-10f);
        __syncthreads();
        for (int s2 = 512; s2; s2 >>= 1) {
            if (tid < s2) red[tid] += red[tid + s2];
            __syncthreads();
        }
        if (tid == 0 && out_perp != nullptr) out_perp[s] = expf(-red[0]);
        __syncthreads();
    }
}

// ---------------------------------------------------------------------------
extern "C" void kernel_launch(void* const* d_in, const int* in_sizes, int n_in,
                              void* d_out, int out_size) {
    const float* z  = (const float*)d_in[0];
    const float* cb = (const float*)d_in[1];
    float* out = (float*)d_out;

    const int N = in_sizes[0] / DIM;          // 32768 rows
    const long qtot = (long)N * DIM;          // 8388608

    float* out_loss = nullptr;
    float* out_comp = nullptr;
    float* out_perp = nullptr;
    if ((long)out_size >= qtot + 1 + N + DEPTH) {
        out_loss = out + qtot;
        out_comp = out + qtot + 1;
        out_perp = out + qtot + 1 + N;
    }

    size_t smem = (size_t)(DIM * AS + 64 * BS) * sizeof(float);  // ~165 KB
    cudaFuncSetAttribute(vq_main_kernel,
                         cudaFuncAttributeMaxDynamicSharedMemorySize, (int)smem);

    vq_init_kernel<<<(DEPTH * KCB + 7) / 8, 256>>>(cb);
    vq_main_kernel<<<N / TM, NTHREADS, smem>>>(z, cb, out, out_comp);
    vq_finalize_kernel<<<1, 1024>>>(out_loss, out_perp, N / TM,
                                    1.0f / (float)qtot, 1.0f / (float)N);
}

// round 12
// speedup vs baseline: 2.1594x; 2.0419x over previous
#include <cuda_runtime.h>
#include <cstdint>

// ---------------------------------------------------------------------------
// MultiStageResidualVQ — R10-R12: bf16 mma.sync.m16n8k16 scores + exact rescue.
// tcgen05 is unavailable (harness targets compute_103 virtual arch; 'a'
// features rejected). Legacy mma.sync (sm_80 ISA) is the only tensor path.
// Scores: A = bf16(exact fp32 residual), B = bf16(codebook), fp32 accum.
// Per row: 4 threads each keep top-4 of their 256-code slice; if the merged
// margin <= BAND, candidates within BAND are exactly rescored in fp32
// (residual recomputed from z - prior codes, same op order as the exact
// R4/R7 kernels). Residual update, SSE, histogram, composed: exact fp32.
// R12: resubmit unchanged — R10/R11 never ran (broker timeouts).
// ---------------------------------------------------------------------------

#define DEPTH 3
#define KCB   1024
#define DIM   256
#define TM    128
#define NTHREADS 256
#define NC    128           // codes per chunk
#define NCHUNK 8
#define NKS   16            // K=256 in 16 steps of k=16
#define AHS   264           // bf16 row stride (padded: conflict-free LDS)
#define BAND  2.0f

#define A_BYTES (TM*AHS*2)                 // 67584
#define C_OFF   A_BYTES
#define C_BYTES (NC*AHS*2)                 // 67584
#define H_OFF   (C_OFF + C_BYTES)          // 135168
#define DYN_SMEM (H_OFF + KCB*4)           // 139264

typedef unsigned int u32;
typedef unsigned short u16;

__device__ float d_hE2[DEPTH*KCB];
__device__ int   d_counts[DEPTH*KCB];
__device__ float d_blockSSE[512];

__device__ __forceinline__ u32 bf2(float lo, float hi){
    u32 d; asm("cvt.rn.bf16x2.f32 %0, %1, %2;" : "=r"(d) : "f"(hi), "f"(lo));
    return d;
}
__device__ __forceinline__ void mma16816(float& d0,float& d1,float& d2,float& d3,
                                         u32 a0,u32 a1,u32 a2,u32 a3,u32 b0,u32 b1){
    asm volatile("mma.sync.aligned.m16n8k16.row.col.f32.bf16.bf16.f32 "
        "{%0,%1,%2,%3}, {%4,%5,%6,%7}, {%8,%9}, {%0,%1,%2,%3};"
        : "+f"(d0),"+f"(d1),"+f"(d2),"+f"(d3)
        : "r"(a0),"r"(a1),"r"(a2),"r"(a3),"r"(b0),"r"(b1));
}
__device__ __forceinline__ void ins4(float sc, int code, float* v, int* ix){
    int mp = 0; float mv = v[0];
    if (v[1] < mv) { mv = v[1]; mp = 1; }
    if (v[2] < mv) { mv = v[2]; mp = 2; }
    if (v[3] < mv) { mv = v[3]; mp = 3; }
    if (sc > mv) { v[mp] = sc; ix[mp] = code; }
}

// ---------------------------------------------------------------------------
__global__ void vq_init_kernel(const float* __restrict__ cb) {
    int gid = blockIdx.x * blockDim.x + threadIdx.x;
    if (gid < DEPTH * KCB) d_counts[gid] = 0;

    int warp = threadIdx.x >> 5, lane = threadIdx.x & 31;
    int cw = blockIdx.x * 8 + warp;
    if (cw < DEPTH * KCB) {
        const float* row = cb + (size_t)cw * DIM;
        float s = 0.f;
        #pragma unroll
        for (int i = lane; i < DIM; i += 32) { float v = row[i]; s += v * v; }
        #pragma unroll
        for (int off = 16; off; off >>= 1) s += __shfl_xor_sync(0xffffffffu, s, off);
        if (lane == 0) d_hE2[cw] = 0.5f * s;
    }
}

// ---------------------------------------------------------------------------
extern __shared__ char smraw[];

__global__ __launch_bounds__(NTHREADS, 1)
void vq_main_kernel(const float* __restrict__ z,
                    const float* __restrict__ cb,
                    float* __restrict__ out_q,
                    float* __restrict__ out_comp) {
    u16*  Abf = (u16*)smraw;               // [TM][AHS] bf16 residual
    u16*  Cbf = (u16*)(smraw + C_OFF);     // [NC][AHS] bf16 codebook chunk
    float* Hs = (float*)(smraw + H_OFF);   // 0.5*|e|^2, current stage

    __shared__ int   s_hist[DEPTH][TM];
    __shared__ float s_red[8];

    const int tid = threadIdx.x, wid = tid >> 5, lane = tid & 31;
    const int gid = lane >> 2, tig = lane & 3;
    const int row0 = blockIdx.x * TM;
    const int rowE = tid & 127, halfE = tid >> 7;
    const int rA = wid * 16 + gid, rB = rA + 8;

    float sse = 0.f;

    for (int s = 0; s < DEPTH; ++s) {
        const float* cbs = cb + (size_t)s * KCB * DIM;
        for (int i = tid; i < KCB; i += NTHREADS) Hs[i] = d_hE2[s * KCB + i];

        // ---- build bf16 residual (exact fp32 chain; SSE of prev stage) ----
        {
            int h0 = (s > 0) ? s_hist[0][rowE] : 0;
            int h1 = (s > 1) ? s_hist[1][rowE] : 0;
            const float* c0r = cb + (size_t)h0 * DIM;                 // stage 0 cb
            const float* c1r = cb + (size_t)(KCB + h1) * DIM;         // stage 1 cb
            #pragma unroll 8
            for (int i = 0; i < 128; i += 4) {
                int d = halfE * 128 + i;
                float4 r4 = *(const float4*)(z + (size_t)(row0 + rowE) * DIM + d);
                if (s > 0) {
                    float4 c = *(const float4*)(c0r + d);
                    r4.x -= c.x; r4.y -= c.y; r4.z -= c.z; r4.w -= c.w;
                }
                if (s > 1) {
                    float4 c = *(const float4*)(c1r + d);
                    r4.x -= c.x; r4.y -= c.y; r4.z -= c.z; r4.w -= c.w;
                }
                if (s > 0)  // SSE of stage s-1 residual
                    sse += r4.x*r4.x + r4.y*r4.y + r4.z*r4.z + r4.w*r4.w;
                u32* dst = (u32*)(Abf + rowE * AHS + d);
                dst[0] = bf2(r4.x, r4.y);
                dst[1] = bf2(r4.z, r4.w);
            }
        }
        __syncthreads();

        float vA[4], vB[4]; int iA[4], iB[4];
        #pragma unroll
        for (int j = 0; j < 4; ++j) {
            vA[j] = -1e30f; vB[j] = -1e30f; iA[j] = 0; iB[j] = 0;
        }

        for (int c = 0; c < NCHUNK; ++c) {
            // ---- codebook chunk -> bf16 SMEM ----
            #pragma unroll
            for (int u = 0; u < 64; ++u) {
                int lin = tid + u * NTHREADS;          // 0..16383
                int code = lin >> 7, c2 = lin & 127;
                float2 w2 = *(const float2*)(cbs + (size_t)(c * NC + code) * DIM + c2 * 2);
                *((u32*)(Cbf + code * AHS) + c2) = bf2(w2.x, w2.y);
            }
            __syncthreads();

            float acc[16][4];
            #pragma unroll
            for (int nt = 0; nt < 16; ++nt)
                #pragma unroll
                for (int q = 0; q < 4; ++q) acc[nt][q] = 0.f;

            #pragma unroll
            for (int ks = 0; ks < NKS; ++ks) {
                int k0 = ks * 16;
                u32 a0 = *(const u32*)(Abf + rA * AHS + k0 + tig * 2);
                u32 a1 = *(const u32*)(Abf + rB * AHS + k0 + tig * 2);
                u32 a2 = *(const u32*)(Abf + rA * AHS + k0 + tig * 2 + 8);
                u32 a3 = *(const u32*)(Abf + rB * AHS + k0 + tig * 2 + 8);
                #pragma unroll
                for (int nt = 0; nt < 16; ++nt) {
                    const u16* bp = Cbf + (nt * 8 + gid) * AHS + k0 + tig * 2;
                    u32 b0 = *(const u32*)bp;
                    u32 b1 = *(const u32*)(bp + 8);
                    mma16816(acc[nt][0], acc[nt][1], acc[nt][2], acc[nt][3],
                             a0, a1, a2, a3, b0, b1);
                }
            }

            // ---- fold into per-thread top-4 (rows rA, rB) ----
            #pragma unroll
            for (int nt = 0; nt < 16; ++nt) {
                int code0 = c * NC + nt * 8 + tig * 2;
                float h0 = Hs[code0], h1 = Hs[code0 + 1];
                ins4(acc[nt][0] - h0, code0,     vA, iA);
                ins4(acc[nt][1] - h1, code0 + 1, vA, iA);
                ins4(acc[nt][2] - h0, code0,     vB, iB);
                ins4(acc[nt][3] - h1, code0 + 1, vB, iB);
            }
            __syncthreads();    // before next chunk overwrites Cbf
        }

        // ---- selection: merge 4 threads/row, gated exact rescore ----
        #pragma unroll
        for (int rr = 0; rr < 2; ++rr) {
            float* v = rr ? vB : vA;
            int*   ix = rr ? iB : iA;
            int    r = rr ? rB : rA;

            // local top2 (index tie -> smaller)
            float l1 = -1e30f, l2 = -1e30f; int li = 0x7fffffff;
            #pragma unroll
            for (int j = 0; j < 4; ++j) {
                if (v[j] > l1 || (v[j] == l1 && ix[j] < li)) { l2 = l1; l1 = v[j]; li = ix[j]; }
                else if (v[j] > l2) l2 = v[j];
            }
            // butterfly merge across the 4 tig-threads
            #pragma unroll
            for (int off = 1; off <= 2; off <<= 1) {
                float o1 = __shfl_xor_sync(0xffffffffu, l1, off);
                float o2 = __shfl_xor_sync(0xffffffffu, l2, off);
                int   oi = __shfl_xor_sync(0xffffffffu, li, off);
                if (o1 > l1 || (o1 == l1 && oi < li)) { l2 = fmaxf(l1, o2); l1 = o1; li = oi; }
                else { l2 = fmaxf(l2, o1); }
            }

            bool need = (l1 - l2 <= BAND);
            float ev = -1e30f; int ei = 0x7fffffff;
            if (need) {
                int h0 = (s > 0) ? s_hist[0][r] : 0;
                int h1 = (s > 1) ? s_hist[1][r] : 0;
                const float* c0r = cb + (size_t)h0 * DIM;
                const float* c1r = cb + (size_t)(KCB + h1) * DIM;
                #pragma unroll
                for (int j = 0; j < 4; ++j) {
                    if (v[j] < l1 - BAND) continue;
                    const float* crow = cbs + (size_t)ix[j] * DIM;
                    float p0 = 0.f, p1 = 0.f, p2 = 0.f, p3 = 0.f;
                    for (int d = 0; d < DIM; d += 4) {
                        float4 r4 = *(const float4*)(z + (size_t)(row0 + r) * DIM + d);
                        if (s > 0) {
                            float4 cc = *(const float4*)(c0r + d);
                            r4.x -= cc.x; r4.y -= cc.y; r4.z -= cc.z; r4.w -= cc.w;
                        }
                        if (s > 1) {
                            float4 cc = *(const float4*)(c1r + d);
                            r4.x -= cc.x; r4.y -= cc.y; r4.z -= cc.z; r4.w -= cc.w;
                        }
                        float4 cd = *(const float4*)(crow + d);
                        p0 = fmaf(r4.x, cd.x, p0); p1 = fmaf(r4.y, cd.y, p1);
                        p2 = fmaf(r4.z, cd.z, p2); p3 = fmaf(r4.w, cd.w, p3);
                    }
                    float e = ((p0 + p1) + (p2 + p3)) - Hs[ix[j]];
                    if (e > ev || (e == ev && ix[j] < ei)) { ev = e; ei = ix[j]; }
                }
            }
            // unconditional combine (uniform shfl)
            #pragma unroll
            for (int off = 1; off <= 2; off <<= 1) {
                float ov = __shfl_xor_sync(0xffffffffu, ev, off);
                int   oi = __shfl_xor_sync(0xffffffffu, ei, off);
                if (ov > ev || (ov == ev && oi < ei)) { ev = ov; ei = oi; }
            }
            int idx = need ? ei : li;
            if (tig == 0) {
                s_hist[s][r] = idx;
                atomicAdd(&d_counts[s * KCB + idx], 1);
            }
        }
        __syncthreads();   // s_hist visible to next stage / epilogue
    }

    // ---- epilogue: exact res_final, q_total, stage-2 SSE ----
    {
        int h0 = s_hist[0][rowE], h1 = s_hist[1][rowE], h2 = s_hist[2][rowE];
        const float* c0r = cb + (size_t)h0 * DIM;
        const float* c1r = cb + (size_t)(KCB + h1) * DIM;
        const float* c2r = cb + (size_t)(2 * KCB + h2) * DIM;
        #pragma unroll 8
        for (int i = 0; i < 128; i += 4) {
            int d = halfE * 128 + i;
            float4 zv = *(const float4*)(z + (size_t)(row0 + rowE) * DIM + d);
            float4 a = zv;
            float4 c0 = *(const float4*)(c0r + d);
            a.x -= c0.x; a.y -= c0.y; a.z -= c0.z; a.w -= c0.w;
            float4 c1 = *(const float4*)(c1r + d);
            a.x -= c1.x; a.y -= c1.y; a.z -= c1.z; a.w -= c1.w;
            float4 c2 = *(const float4*)(c2r + d);
            a.x -= c2.x; a.y -= c2.y; a.z -= c2.z; a.w -= c2.w;
            sse += a.x*a.x + a.y*a.y + a.z*a.z + a.w*a.w;
            float4 o;
            o.x = zv.x - a.x; o.y = zv.y - a.y; o.z = zv.z - a.z; o.w = zv.w - a.w;
            *(float4*)(out_q + (size_t)(row0 + rowE) * DIM + d) = o;
        }
    }

    if (out_comp != nullptr && tid < TM)
        out_comp[row0 + tid] = (float)(s_hist[0][tid] + s_hist[1][tid] * 1024
                                       + s_hist[2][tid] * 1048576);

    // ---- deterministic per-block SSE partial ----
    #pragma unroll
    for (int off = 16; off; off >>= 1) sse += __shfl_xor_sync(0xffffffffu, sse, off);
    if (lane == 0) s_red[wid] = sse;
    __syncthreads();
    if (tid == 0) {
        float t = 0.f;
        #pragma unroll
        for (int w = 0; w < 8; ++w) t += s_red[w];
        d_blockSSE[blockIdx.x] = t;
    }
}

// ---------------------------------------------------------------------------
__global__ void vq_finalize_kernel(float* out_loss, float* out_perp,
                                   int nblocks, float inv_total, float inv_n) {
    __shared__ float red[1024];
    int tid = threadIdx.x;

    float v = (tid < nblocks) ? d_blockSSE[tid] : 0.f;
    red[tid] = v;
    __syncthreads();
    for (int s2 = 512; s2; s2 >>= 1) {
        if (tid < s2) red[tid] += red[tid + s2];
        __syncthreads();
    }
    if (tid == 0 && out_loss != nullptr)
        *out_loss = 1.25f * red[0] * inv_total;
    __syncthreads();

    for (int s = 0; s < DEPTH; ++s) {
        float p = (float)d_counts[s * KCB + tid] * inv_n;
        red[tid] = p * logf(p + 1e-10f);
        __syncthreads();
        for (int s2 = 512; s2; s2 >>= 1) {
            if (tid < s2) red[tid] += red[tid + s2];
            __syncthreads();
        }
        if (tid == 0 && out_perp != nullptr) out_perp[s] = expf(-red[0]);
        __syncthreads();
    }
}

// ---------------------------------------------------------------------------
extern "C" void kernel_launch(void* const* d_in, const int* in_sizes, int n_in,
                              void* d_out, int out_size) {
    const float* z  = (const float*)d_in[0];
    const float* cb = (const float*)d_in[1];
    float* out = (float*)d_out;

    const int N = in_sizes[0] / DIM;          // 32768 rows
    const long qtot = (long)N * DIM;

    float* out_loss = nullptr;
    float* out_comp = nullptr;
    float* out_perp = nullptr;
    if ((long)out_size >= qtot + 1 + N + DEPTH) {
        out_loss = out + qtot;
        out_comp = out + qtot + 1;
        out_perp = out + qtot + 1 + N;
    }

    cudaFuncSetAttribute(vq_main_kernel,
                         cudaFuncAttributeMaxDynamicSharedMemorySize, DYN_SMEM);

    vq_init_kernel<<<(DEPTH * KCB + 7) / 8, 256>>>(cb);
    vq_main_kernel<<<N / TM, NTHREADS, DYN_SMEM>>>(z, cb, out, out_comp);
    vq_finalize_kernel<<<1, 1024>>>(out_loss, out_perp, N / TM,
                                    1.0f / (float)qtot, 1.0f / (float)N);
}